// round 2
// baseline (speedup 1.0000x reference)
#include <cuda_runtime.h>

static constexpr long kQSize = 256L * 128 * 512;        // 16,777,216
static constexpr long kAttn  = 8L * 256 * 128 * 256;    // 67,108,864

__device__ float g_lnL[kQSize];
__device__ float g_lnR[kQSize];
__device__ float g_q[kQSize];          // [w][n][c], pre-scaled by 0.125
__device__ float g_kv[2 * kQSize];     // [w][n][k(0:512)|v(512:1024)]
__device__ float g_posp[511 * 1024];   // [p][q_r*0.125 (0:512) | k_r (512:1024)]
__device__ float g_vo[kQSize];         // [w][n][c]
__device__ float g_A12[kAttn];         // [e][w][n][v]  scores -> probs
__device__ float g_T3[kAttn];          // [e][v][w][n]

__device__ __forceinline__ float4 ld4(const float* p) {
  return *reinterpret_cast<const float4*>(p);
}

// ---------------- LayerNorm: one block per 512-float row ----------------
__global__ void __launch_bounds__(128) ln_kernel(const float* __restrict__ fl,
                                                 const float* __restrict__ fr,
                                                 const float* __restrict__ lw,
                                                 const float* __restrict__ lb) {
  long row = blockIdx.x;
  const float* src;
  float* dst;
  if (row < 32768) { src = fl + row * 512;           dst = g_lnL + row * 512; }
  else             { src = fr + (row - 32768) * 512; dst = g_lnR + (row - 32768) * 512; }
  int t = threadIdx.x;
  float4 x = ld4(src + t * 4);
  float s  = x.x + x.y + x.z + x.w;
  float q2 = x.x * x.x + x.y * x.y + x.z * x.z + x.w * x.w;
#pragma unroll
  for (int o = 16; o > 0; o >>= 1) {
    s  += __shfl_xor_sync(0xffffffffu, s, o);
    q2 += __shfl_xor_sync(0xffffffffu, q2, o);
  }
  __shared__ float ss[4], sq[4];
  if ((t & 31) == 0) { ss[t >> 5] = s; sq[t >> 5] = q2; }
  __syncthreads();
  s  = ss[0] + ss[1] + ss[2] + ss[3];
  q2 = sq[0] + sq[1] + sq[2] + sq[3];
  float mean = s * (1.f / 512.f);
  float var  = q2 * (1.f / 512.f) - mean * mean;
  float rstd = rsqrtf(var + 1e-5f);
  float4 wv = ld4(lw + t * 4), bv = ld4(lb + t * 4);
  float4 o;
  o.x = (x.x - mean) * rstd * wv.x + bv.x;
  o.y = (x.y - mean) * rstd * wv.y + bv.y;
  o.z = (x.z - mean) * rstd * wv.z + bv.z;
  o.w = (x.w - mean) * rstd * wv.w + bv.w;
  *reinterpret_cast<float4*>(dst + t * 4) = o;
}

// ---------------- Tiled GEMM, specialized by MODE ----------------
// 0: q = lnL@Wq^T (+b)*0.125 -> g_q         1: kv = lnR@Wkv^T + b -> g_kv
// 2: posp = pos@W[:1024]^T + b (cols<512 *0.125), M=511 guarded -> g_posp
// 3: T1 per (n,e): q.k^T -> A12             4: T2 per (e,w): q.kr^T += A12 (gather B)
// 5: T3 per (e,v): qr.k^T -> T3 (gather A)  6: AV per (n,e): P@V (NN) -> g_vo
// 7: out = vo@Wo^T + b + resid -> d_out
template <int MODE, int BM, int BN, int TM, int TN>
__global__ void __launch_bounds__((BM / TM) * (BN / TN))
gemm_k(const float* __restrict__ pA, const float* __restrict__ pB,
       const float* __restrict__ pbias, const float* __restrict__ presid,
       const int* __restrict__ pidx, float* __restrict__ pC) {
  constexpr int NT = (BM / TM) * (BN / TN);
  constexpr int BK = 16;
  __shared__ float As[BK][BM + 4];
  __shared__ float Bs[BK][BN + 4];

  const int tid = threadIdx.x;
  const int tx = tid % (BN / TN);
  const int ty = tid / (BN / TN);
  const int i0 = blockIdx.y * BM;
  const int j0 = blockIdx.x * BN;
  const int z  = blockIdx.z;

  const float* A = nullptr;
  const float* B = nullptr;
  float* C = nullptr;
  long lda = 0, ldb = 0, ldc = 0;
  int K = 0, e = 0, bb = 0;

  if constexpr (MODE == 0) { A = g_lnL; lda = 512; K = 512; B = pB; ldb = 512; C = g_q; ldc = 512; }
  else if constexpr (MODE == 1) { A = g_lnR; lda = 512; K = 512; B = pB; ldb = 512; C = g_kv; ldc = 1024; }
  else if constexpr (MODE == 2) { A = pA; lda = 512; K = 512; B = pB; ldb = 512; C = g_posp; ldc = 1024; }
  else if constexpr (MODE == 3) { bb = z >> 3; e = z & 7;
    A = g_q + (long)bb * 512 + e * 64; lda = 65536; K = 64;
    B = g_kv + (long)bb * 1024 + e * 64; ldb = 131072;
    C = g_A12 + (long)e * 8388608 + (long)bb * 256; ldc = 32768; }
  else if constexpr (MODE == 4) { e = z >> 8; bb = z & 255;
    A = g_q + (long)bb * 65536 + e * 64; lda = 512; K = 64;
    C = g_A12 + (long)e * 8388608 + (long)bb * 32768; ldc = 256; }
  else if constexpr (MODE == 5) { e = z >> 8; bb = z & 255;
    B = g_kv + (long)bb * 131072 + e * 64; ldb = 1024; K = 64;
    C = g_T3 + ((long)e * 256 + bb) * 32768; ldc = 128; }
  else if constexpr (MODE == 6) { bb = z >> 3; e = z & 7;
    A = g_A12 + (long)e * 8388608 + (long)bb * 256; lda = 32768; K = 256;
    B = g_kv + (long)bb * 1024 + 512 + e * 64; ldb = 131072;
    C = g_vo + (long)bb * 512 + e * 64; ldc = 65536; }
  else { A = g_vo; lda = 512; K = 512; B = pB; ldb = 512; C = pC; ldc = 512; }

  float acc[TM][TN];
#pragma unroll
  for (int m = 0; m < TM; ++m)
#pragma unroll
    for (int n = 0; n < TN; ++n) acc[m][n] = 0.f;

  for (int k0 = 0; k0 < K; k0 += BK) {
    // ---- A tile (BM x BK) ----
    if constexpr (MODE == 5) {
#pragma unroll
      for (int it = 0; it < (BM * BK) / (NT * 4); ++it) {
        int t = tid * 4 + it * NT * 4;
        int i = t >> 4, kk = t & 15;
        int gi = pidx[(i0 + i) * 256 + bb];
        float4 v4 = ld4(g_posp + (long)gi * 1024 + e * 64 + k0 + kk);
        As[kk][i] = v4.x; As[kk + 1][i] = v4.y; As[kk + 2][i] = v4.z; As[kk + 3][i] = v4.w;
      }
    } else {
#pragma unroll
      for (int it = 0; it < (BM * BK) / (NT * 4); ++it) {
        int t = tid * 4 + it * NT * 4;
        int i = t >> 4, kk = t & 15;
        float4 v4;
        if constexpr (MODE == 2) {
          v4 = (i0 + i < 511) ? ld4(A + (long)(i0 + i) * lda + k0 + kk)
                              : make_float4(0.f, 0.f, 0.f, 0.f);
        } else {
          v4 = ld4(A + (long)(i0 + i) * lda + k0 + kk);
        }
        As[kk][i] = v4.x; As[kk + 1][i] = v4.y; As[kk + 2][i] = v4.z; As[kk + 3][i] = v4.w;
      }
    }
    // ---- B tile ----
    if constexpr (MODE == 6) {  // NN: B[k][j]
#pragma unroll
      for (int it = 0; it < (BK * BN) / (NT * 4); ++it) {
        int t = tid * 4 + it * NT * 4;
        int kk = t / BN, j = t % BN;
        float4 v4 = ld4(B + (long)(k0 + kk) * ldb + j0 + j);
        *reinterpret_cast<float4*>(&Bs[kk][j]) = v4;
      }
    } else if constexpr (MODE == 4) {  // gathered NT
#pragma unroll
      for (int it = 0; it < (BN * BK) / (NT * 4); ++it) {
        int t = tid * 4 + it * NT * 4;
        int j = t >> 4, kk = t & 15;
        int gi = pidx[bb * 256 + j0 + j];
        float4 v4 = ld4(g_posp + (long)gi * 1024 + 512 + e * 64 + k0 + kk);
        Bs[kk][j] = v4.x; Bs[kk + 1][j] = v4.y; Bs[kk + 2][j] = v4.z; Bs[kk + 3][j] = v4.w;
      }
    } else {  // NT: B[j][k]
#pragma unroll
      for (int it = 0; it < (BN * BK) / (NT * 4); ++it) {
        int t = tid * 4 + it * NT * 4;
        int j = t >> 4, kk = t & 15;
        float4 v4 = ld4(B + (long)(j0 + j) * ldb + k0 + kk);
        Bs[kk][j] = v4.x; Bs[kk + 1][j] = v4.y; Bs[kk + 2][j] = v4.z; Bs[kk + 3][j] = v4.w;
      }
    }
    __syncthreads();
#pragma unroll
    for (int kk = 0; kk < BK; ++kk) {
      float ra[TM], rb[TN];
#pragma unroll
      for (int m = 0; m < TM; m += 4)
        *reinterpret_cast<float4*>(&ra[m]) =
            *reinterpret_cast<const float4*>(&As[kk][ty * TM + m]);
#pragma unroll
      for (int n = 0; n < TN; n += 4)
        *reinterpret_cast<float4*>(&rb[n]) =
            *reinterpret_cast<const float4*>(&Bs[kk][tx * TN + n]);
#pragma unroll
      for (int m = 0; m < TM; ++m)
#pragma unroll
        for (int n = 0; n < TN; ++n) acc[m][n] += ra[m] * rb[n];
    }
    __syncthreads();
  }

  // ---- epilogue ----
#pragma unroll
  for (int m = 0; m < TM; ++m) {
    int i = i0 + ty * TM + m;
    if constexpr (MODE == 2) { if (i >= 511) continue; }
    float* crow = C + (long)i * ldc;
#pragma unroll
    for (int n = 0; n < TN; n += 4) {
      int j = j0 + tx * TN + n;
      float4 r = make_float4(acc[m][n], acc[m][n + 1], acc[m][n + 2], acc[m][n + 3]);
      if constexpr (MODE == 0) {
        float4 bv = ld4(pbias + j);
        r.x = (r.x + bv.x) * 0.125f; r.y = (r.y + bv.y) * 0.125f;
        r.z = (r.z + bv.z) * 0.125f; r.w = (r.w + bv.w) * 0.125f;
      } else if constexpr (MODE == 1) {
        float4 bv = ld4(pbias + j);
        r.x += bv.x; r.y += bv.y; r.z += bv.z; r.w += bv.w;
      } else if constexpr (MODE == 2) {
        float4 bv = ld4(pbias + j);
        float sc = (j < 512) ? 0.125f : 1.0f;
        r.x = (r.x + bv.x) * sc; r.y = (r.y + bv.y) * sc;
        r.z = (r.z + bv.z) * sc; r.w = (r.w + bv.w) * sc;
      } else if constexpr (MODE == 4) {
        float4 o = ld4(crow + j);
        r.x += o.x; r.y += o.y; r.z += o.z; r.w += o.w;
      } else if constexpr (MODE == 7) {
        float4 bv = ld4(pbias + j);
        float4 rv = ld4(presid + (long)i * 512 + j);
        r.x += bv.x + rv.x; r.y += bv.y + rv.y;
        r.z += bv.z + rv.z; r.w += bv.w + rv.w;
      }
      *reinterpret_cast<float4*>(crow + j) = r;
    }
  }
}

// ---------------- T3 transpose-add: A12[e][w][n][v] += T3[e][v][w][n] ----------------
__global__ void __launch_bounds__(256) t3_add_kernel() {
  int w = blockIdx.x, e = blockIdx.y;
  __shared__ float ts[32][129];
  long a12base = (long)e * 8388608 + (long)w * 32768;
  long t3base  = (long)e * 256 * 32768 + (long)w * 128;
  for (int v0 = 0; v0 < 256; v0 += 32) {
    for (int t = threadIdx.x; t < 32 * 128; t += 256) {
      int vj = t >> 7, n = t & 127;
      ts[vj][n] = g_T3[t3base + (long)(v0 + vj) * 32768 + n];
    }
    __syncthreads();
    for (int t = threadIdx.x; t < 32 * 128; t += 256) {
      int n = t >> 5, vj = t & 31;
      g_A12[a12base + n * 256 + v0 + vj] += ts[vj][n];
    }
    __syncthreads();
  }
}

// ---------------- raw_attn[n][w][v] = sum_e A12[e][w][n][v] ----------------
__global__ void __launch_bounds__(256) raw_kernel(float* __restrict__ out2) {
  int wn = blockIdx.x;
  int w = wn >> 7, n = wn & 127;
  int v = threadIdx.x;
  float s = 0.f;
#pragma unroll
  for (int e = 0; e < 8; ++e)
    s += g_A12[(((long)e * 256 + w) * 128 + n) * 256 + v];
  out2[((long)n * 256 + w) * 256 + v] = s;
}

// ---------------- softmax over last dim (256) in place ----------------
__global__ void __launch_bounds__(256) softmax_kernel() {
  long row = (long)blockIdx.x * 8 + (threadIdx.x >> 5);
  int lane = threadIdx.x & 31;
  float* p = g_A12 + row * 256;
  float4 a = ld4(p + lane * 4);
  float4 b = ld4(p + 128 + lane * 4);
  float mx = fmaxf(fmaxf(fmaxf(a.x, a.y), fmaxf(a.z, a.w)),
                   fmaxf(fmaxf(b.x, b.y), fmaxf(b.z, b.w)));
#pragma unroll
  for (int o = 16; o > 0; o >>= 1) mx = fmaxf(mx, __shfl_xor_sync(0xffffffffu, mx, o));
  a.x = __expf(a.x - mx); a.y = __expf(a.y - mx);
  a.z = __expf(a.z - mx); a.w = __expf(a.w - mx);
  b.x = __expf(b.x - mx); b.y = __expf(b.y - mx);
  b.z = __expf(b.z - mx); b.w = __expf(b.w - mx);
  float s = a.x + a.y + a.z + a.w + b.x + b.y + b.z + b.w;
#pragma unroll
  for (int o = 16; o > 0; o >>= 1) s += __shfl_xor_sync(0xffffffffu, s, o);
  float inv = 1.0f / s;
  a.x *= inv; a.y *= inv; a.z *= inv; a.w *= inv;
  b.x *= inv; b.y *= inv; b.z *= inv; b.w *= inv;
  *reinterpret_cast<float4*>(p + lane * 4) = a;
  *reinterpret_cast<float4*>(p + 128 + lane * 4) = b;
}

extern "C" void kernel_launch(void* const* d_in, const int* in_sizes, int n_in,
                              void* d_out, int out_size) {
  const float* feat_left   = (const float*)d_in[0];
  const float* feat_right  = (const float*)d_in[1];
  const float* pos         = (const float*)d_in[2];
  const int*   pos_indexes = (const int*)d_in[3];
  const float* ln_w        = (const float*)d_in[4];
  const float* ln_b        = (const float*)d_in[5];
  const float* in_proj_w   = (const float*)d_in[6];
  const float* in_proj_b   = (const float*)d_in[7];
  const float* out_w       = (const float*)d_in[8];
  const float* out_b       = (const float*)d_in[9];
  float* out = (float*)d_out;

  ln_kernel<<<65536, 128>>>(feat_left, feat_right, ln_w, ln_b);

  gemm_k<0, 128, 128, 8, 8><<<dim3(4, 256, 1), 256>>>(
      nullptr, in_proj_w, in_proj_b, nullptr, nullptr, nullptr);
  gemm_k<1, 128, 128, 8, 8><<<dim3(8, 256, 1), 256>>>(
      nullptr, in_proj_w + 512 * 512, in_proj_b + 512, nullptr, nullptr, nullptr);
  gemm_k<2, 128, 128, 8, 8><<<dim3(8, 4, 1), 256>>>(
      pos, in_proj_w, in_proj_b, nullptr, nullptr, nullptr);

  gemm_k<3, 128, 128, 8, 8><<<dim3(2, 2, 1024), 256>>>(
      nullptr, nullptr, nullptr, nullptr, nullptr, nullptr);
  gemm_k<4, 128, 128, 8, 8><<<dim3(2, 1, 2048), 256>>>(
      nullptr, nullptr, nullptr, nullptr, pos_indexes, nullptr);
  gemm_k<5, 128, 128, 8, 8><<<dim3(1, 2, 2048), 256>>>(
      nullptr, nullptr, nullptr, nullptr, pos_indexes, nullptr);

  t3_add_kernel<<<dim3(256, 8), 256>>>();
  raw_kernel<<<32768, 256>>>(out + 16777216);
  softmax_kernel<<<32768, 256>>>();

  gemm_k<6, 128, 64, 8, 4><<<dim3(1, 2, 1024), 256>>>(
      nullptr, nullptr, nullptr, nullptr, nullptr, nullptr);
  gemm_k<7, 128, 128, 8, 8><<<dim3(4, 256, 1), 256>>>(
      nullptr, out_w, out_b, feat_left, nullptr, out);
}

// round 3
// speedup vs baseline: 1.8618x; 1.8618x over previous
#include <cuda_runtime.h>

static constexpr long kQSize = 256L * 128 * 512;        // 16,777,216
static constexpr long kAttn  = 8L * 256 * 128 * 256;    // 67,108,864

__device__ float g_lnL[kQSize];
__device__ float g_lnR[kQSize];
__device__ float g_q[kQSize];          // [w][n][c], pre-scaled by 0.125
__device__ float g_kv[2 * kQSize];     // [w][n][k(0:512)|v(512:1024)]
__device__ float g_posp[511 * 1024];   // [p][q_r*0.125 (0:512) | k_r (512:1024)]
__device__ float g_vo[kQSize];         // [w][n][c]
__device__ float g_A12[kAttn];         // [e][w][n][v]  scores -> probs
__device__ float g_T3[kAttn];          // [e][v][w][n]

__device__ __forceinline__ float4 ld4(const float* p) {
  return *reinterpret_cast<const float4*>(p);
}
__device__ __forceinline__ unsigned f2tf(float x) {
  unsigned r;
  asm("cvt.rna.tf32.f32 %0, %1;" : "=r"(r) : "f"(x));
  return r;
}
__device__ __forceinline__ void mma8(float (&d)[4], const unsigned (&a)[4],
                                     const unsigned (&b)[2]) {
  asm("mma.sync.aligned.m16n8k8.row.col.f32.tf32.tf32.f32 "
      "{%0,%1,%2,%3}, {%4,%5,%6,%7}, {%8,%9}, {%0,%1,%2,%3};"
      : "+f"(d[0]), "+f"(d[1]), "+f"(d[2]), "+f"(d[3])
      : "r"(a[0]), "r"(a[1]), "r"(a[2]), "r"(a[3]), "r"(b[0]), "r"(b[1]));
}

// ---------------- LayerNorm: one block per 512-float row ----------------
__global__ void __launch_bounds__(128) ln_kernel(const float* __restrict__ fl,
                                                 const float* __restrict__ fr,
                                                 const float* __restrict__ lw,
                                                 const float* __restrict__ lb) {
  long row = blockIdx.x;
  const float* src;
  float* dst;
  if (row < 32768) { src = fl + row * 512;           dst = g_lnL + row * 512; }
  else             { src = fr + (row - 32768) * 512; dst = g_lnR + (row - 32768) * 512; }
  int t = threadIdx.x;
  float4 x = ld4(src + t * 4);
  float s  = x.x + x.y + x.z + x.w;
  float q2 = x.x * x.x + x.y * x.y + x.z * x.z + x.w * x.w;
#pragma unroll
  for (int o = 16; o > 0; o >>= 1) {
    s  += __shfl_xor_sync(0xffffffffu, s, o);
    q2 += __shfl_xor_sync(0xffffffffu, q2, o);
  }
  __shared__ float ss[4], sq[4];
  if ((t & 31) == 0) { ss[t >> 5] = s; sq[t >> 5] = q2; }
  __syncthreads();
  s  = ss[0] + ss[1] + ss[2] + ss[3];
  q2 = sq[0] + sq[1] + sq[2] + sq[3];
  float mean = s * (1.f / 512.f);
  float var  = q2 * (1.f / 512.f) - mean * mean;
  float rstd = rsqrtf(var + 1e-5f);
  float4 wv = ld4(lw + t * 4), bv = ld4(lb + t * 4);
  float4 o;
  o.x = (x.x - mean) * rstd * wv.x + bv.x;
  o.y = (x.y - mean) * rstd * wv.y + bv.y;
  o.z = (x.z - mean) * rstd * wv.z + bv.z;
  o.w = (x.w - mean) * rstd * wv.w + bv.w;
  *reinterpret_cast<float4*>(dst + t * 4) = o;
}

// ---------------- Tensor-core tf32 GEMM, specialized by MODE ----------------
// 0: q = lnL@Wq^T (+b)*0.125 -> g_q         1: kv = lnR@Wkv^T + b -> g_kv
// 2: posp = pos@W[:1024]^T + b (cols<512 *0.125), M=511 guarded -> g_posp
// 3: T1 per (n,e): q.k^T -> A12             4: T2 per (e,w): q.kr^T += A12 (gather B)
// 5: T3 per (e,v): qr.k^T -> T3 (gather A)  6: AV per (n,e): P@V (NN) -> g_vo
// 7: out = vo@Wo^T + b + resid -> d_out
template <int MODE, int BM, int BN>
__global__ void __launch_bounds__(256)
gemm_k(const float* __restrict__ pA, const float* __restrict__ pB,
       const float* __restrict__ pbias, const float* __restrict__ presid,
       const int* __restrict__ pidx, float* __restrict__ pC) {
  constexpr int WGN = BN / 32;       // warps along n
  constexpr int WGM = 8 / WGN;       // warps along m
  constexpr int WM  = BM / WGM;      // rows per warp
  constexpr int MT  = WM / 16;       // 16-row mma tiles per warp
  // smem: As[m][k] (k-pad to 20), Bs either [n][k] (pad 20) or [k][n] (pad to 136)
  __shared__ unsigned As[BM * 20];
  __shared__ unsigned Bs[(MODE == 6) ? 16 * 136 : BN * 20];

  const int tid   = threadIdx.x;
  const int warp  = tid >> 5;
  const int lane  = tid & 31;
  const int gid   = lane >> 2;   // group id (row within fragment)
  const int tg    = lane & 3;    // thread in group (k / col pair)
  const int wm0   = (warp / WGN) * WM;
  const int wn0   = (warp % WGN) * 32;
  const int i0 = blockIdx.y * BM;
  const int j0 = blockIdx.x * BN;
  const int z  = blockIdx.z;

  const float* A = nullptr;
  const float* B = nullptr;
  float* C = nullptr;
  long lda = 0, ldb = 0, ldc = 0;
  int K = 0, e = 0, bb = 0;

  if constexpr (MODE == 0) { A = g_lnL; lda = 512; K = 512; B = pB; ldb = 512; C = g_q; ldc = 512; }
  else if constexpr (MODE == 1) { A = g_lnR; lda = 512; K = 512; B = pB; ldb = 512; C = g_kv; ldc = 1024; }
  else if constexpr (MODE == 2) { A = pA; lda = 512; K = 512; B = pB; ldb = 512; C = g_posp; ldc = 1024; }
  else if constexpr (MODE == 3) { bb = z >> 3; e = z & 7;
    A = g_q + (long)bb * 512 + e * 64; lda = 65536; K = 64;
    B = g_kv + (long)bb * 1024 + e * 64; ldb = 131072;
    C = g_A12 + (long)e * 8388608 + (long)bb * 256; ldc = 32768; }
  else if constexpr (MODE == 4) { e = z >> 8; bb = z & 255;
    A = g_q + (long)bb * 65536 + e * 64; lda = 512; K = 64;
    C = g_A12 + (long)e * 8388608 + (long)bb * 32768; ldc = 256; }
  else if constexpr (MODE == 5) { e = z >> 8; bb = z & 255;
    B = g_kv + (long)bb * 131072 + e * 64; ldb = 1024; K = 64;
    C = g_T3 + ((long)e * 256 + bb) * 32768; ldc = 128; }
  else if constexpr (MODE == 6) { bb = z >> 3; e = z & 7;
    A = g_A12 + (long)e * 8388608 + (long)bb * 256; lda = 32768; K = 256;
    B = g_kv + (long)bb * 1024 + 512 + e * 64; ldb = 131072;
    C = g_vo + (long)bb * 512 + e * 64; ldc = 65536; }
  else { A = g_vo; lda = 512; K = 512; B = pB; ldb = 512; C = pC; ldc = 512; }

  float acc[MT][4][4];
#pragma unroll
  for (int m = 0; m < MT; ++m)
#pragma unroll
    for (int n = 0; n < 4; ++n)
#pragma unroll
      for (int r = 0; r < 4; ++r) acc[m][n][r] = 0.f;

  for (int k0 = 0; k0 < K; k0 += 16) {
    // ---- A tile: BM x 16, stored As[i][k] with tf32 conversion ----
#pragma unroll
    for (int it = 0; it < (BM * 16) / 1024; ++it) {
      int t = (tid + it * 256) * 4;
      int i = t >> 4, kk = t & 15;
      float4 v4;
      if constexpr (MODE == 5) {
        int gi = pidx[(i0 + i) * 256 + bb];
        v4 = ld4(g_posp + (long)gi * 1024 + e * 64 + k0 + kk);
      } else if constexpr (MODE == 2) {
        v4 = (i0 + i < 511) ? ld4(A + (long)(i0 + i) * lda + k0 + kk)
                            : make_float4(0.f, 0.f, 0.f, 0.f);
      } else {
        v4 = ld4(A + (long)(i0 + i) * lda + k0 + kk);
      }
      *reinterpret_cast<uint4*>(&As[i * 20 + kk]) =
          make_uint4(f2tf(v4.x), f2tf(v4.y), f2tf(v4.z), f2tf(v4.w));
    }
    // ---- B tile ----
    if constexpr (MODE == 6) {  // NN: global B[k][j] -> Bs[k*136 + j]
#pragma unroll
      for (int it = 0; it < (16 * BN) / 1024; ++it) {
        int t = (tid + it * 256) * 4;
        int kk = t / BN, j = t % BN;
        float4 v4 = ld4(B + (long)(k0 + kk) * ldb + j0 + j);
        *reinterpret_cast<uint4*>(&Bs[kk * 136 + j]) =
            make_uint4(f2tf(v4.x), f2tf(v4.y), f2tf(v4.z), f2tf(v4.w));
      }
    } else {
#pragma unroll
      for (int it = 0; it < (BN * 16) / 1024; ++it) {
        int t = (tid + it * 256) * 4;
        int j = t >> 4, kk = t & 15;
        float4 v4;
        if constexpr (MODE == 4) {
          int gi = pidx[bb * 256 + j0 + j];
          v4 = ld4(g_posp + (long)gi * 1024 + 512 + e * 64 + k0 + kk);
        } else {
          v4 = ld4(B + (long)(j0 + j) * ldb + k0 + kk);
        }
        *reinterpret_cast<uint4*>(&Bs[j * 20 + kk]) =
            make_uint4(f2tf(v4.x), f2tf(v4.y), f2tf(v4.z), f2tf(v4.w));
      }
    }
    __syncthreads();

#pragma unroll
    for (int ks = 0; ks < 2; ++ks) {
      const int kb = ks * 8;
      unsigned a[MT][4], b[4][2];
#pragma unroll
      for (int mt = 0; mt < MT; ++mt) {
        int r = wm0 + mt * 16 + gid;
        a[mt][0] = As[r * 20 + kb + tg];
        a[mt][1] = As[(r + 8) * 20 + kb + tg];
        a[mt][2] = As[r * 20 + kb + tg + 4];
        a[mt][3] = As[(r + 8) * 20 + kb + tg + 4];
      }
#pragma unroll
      for (int nt = 0; nt < 4; ++nt) {
        int cn = wn0 + nt * 8 + gid;
        if constexpr (MODE == 6) {
          b[nt][0] = Bs[(kb + tg) * 136 + cn];
          b[nt][1] = Bs[(kb + tg + 4) * 136 + cn];
        } else {
          b[nt][0] = Bs[cn * 20 + kb + tg];
          b[nt][1] = Bs[cn * 20 + kb + tg + 4];
        }
      }
#pragma unroll
      for (int mt = 0; mt < MT; ++mt)
#pragma unroll
        for (int nt = 0; nt < 4; ++nt) mma8(acc[mt][nt], a[mt], b[nt]);
    }
    __syncthreads();
  }

  // ---- epilogue: each thread owns pairs (i, j), (i, j+1) and (i+8, ...) ----
#pragma unroll
  for (int mt = 0; mt < MT; ++mt) {
#pragma unroll
    for (int nt = 0; nt < 4; ++nt) {
      int j = j0 + wn0 + nt * 8 + 2 * tg;
#pragma unroll
      for (int h = 0; h < 2; ++h) {
        int i = i0 + wm0 + mt * 16 + gid + h * 8;
        if constexpr (MODE == 2) { if (i >= 511) continue; }
        float v0 = acc[mt][nt][h * 2 + 0];
        float v1 = acc[mt][nt][h * 2 + 1];
        float* cp = C + (long)i * ldc + j;
        if constexpr (MODE == 0) {
          float2 bv = *reinterpret_cast<const float2*>(pbias + j);
          v0 = (v0 + bv.x) * 0.125f; v1 = (v1 + bv.y) * 0.125f;
        } else if constexpr (MODE == 1) {
          float2 bv = *reinterpret_cast<const float2*>(pbias + j);
          v0 += bv.x; v1 += bv.y;
        } else if constexpr (MODE == 2) {
          float2 bv = *reinterpret_cast<const float2*>(pbias + j);
          float sc = (j < 512) ? 0.125f : 1.0f;
          v0 = (v0 + bv.x) * sc; v1 = (v1 + bv.y) * sc;
        } else if constexpr (MODE == 4) {
          float2 o = *reinterpret_cast<const float2*>(cp);
          v0 += o.x; v1 += o.y;
        } else if constexpr (MODE == 7) {
          float2 bv = *reinterpret_cast<const float2*>(pbias + j);
          float2 rv = *reinterpret_cast<const float2*>(presid + (long)i * 512 + j);
          v0 += bv.x + rv.x; v1 += bv.y + rv.y;
        }
        *reinterpret_cast<float2*>(cp) = make_float2(v0, v1);
      }
    }
  }
}

// ---------------- T3 transpose-add: A12[e][w][n][v] += T3[e][v][w][n] ----------------
__global__ void __launch_bounds__(256) t3_add_kernel() {
  int w = blockIdx.x, e = blockIdx.y;
  __shared__ float ts[32][129];
  long a12base = (long)e * 8388608 + (long)w * 32768;
  long t3base  = (long)e * 256 * 32768 + (long)w * 128;
  for (int v0 = 0; v0 < 256; v0 += 32) {
    for (int t = threadIdx.x; t < 32 * 128; t += 256) {
      int vj = t >> 7, n = t & 127;
      ts[vj][n] = g_T3[t3base + (long)(v0 + vj) * 32768 + n];
    }
    __syncthreads();
    for (int t = threadIdx.x; t < 32 * 128; t += 256) {
      int n = t >> 5, vj = t & 31;
      g_A12[a12base + n * 256 + v0 + vj] += ts[vj][n];
    }
    __syncthreads();
  }
}

// ---------------- raw_attn[n][w][v] = sum_e A12[e][w][n][v] ----------------
__global__ void __launch_bounds__(256) raw_kernel(float* __restrict__ out2) {
  int wn = blockIdx.x;
  int w = wn >> 7, n = wn & 127;
  int v = threadIdx.x;
  float s = 0.f;
#pragma unroll
  for (int e = 0; e < 8; ++e)
    s += g_A12[(((long)e * 256 + w) * 128 + n) * 256 + v];
  out2[((long)n * 256 + w) * 256 + v] = s;
}

// ---------------- softmax over last dim (256) in place ----------------
__global__ void __launch_bounds__(256) softmax_kernel() {
  long row = (long)blockIdx.x * 8 + (threadIdx.x >> 5);
  int lane = threadIdx.x & 31;
  float* p = g_A12 + row * 256;
  float4 a = ld4(p + lane * 4);
  float4 b = ld4(p + 128 + lane * 4);
  float mx = fmaxf(fmaxf(fmaxf(a.x, a.y), fmaxf(a.z, a.w)),
                   fmaxf(fmaxf(b.x, b.y), fmaxf(b.z, b.w)));
#pragma unroll
  for (int o = 16; o > 0; o >>= 1) mx = fmaxf(mx, __shfl_xor_sync(0xffffffffu, mx, o));
  a.x = __expf(a.x - mx); a.y = __expf(a.y - mx);
  a.z = __expf(a.z - mx); a.w = __expf(a.w - mx);
  b.x = __expf(b.x - mx); b.y = __expf(b.y - mx);
  b.z = __expf(b.z - mx); b.w = __expf(b.w - mx);
  float s = a.x + a.y + a.z + a.w + b.x + b.y + b.z + b.w;
#pragma unroll
  for (int o = 16; o > 0; o >>= 1) s += __shfl_xor_sync(0xffffffffu, s, o);
  float inv = 1.0f / s;
  a.x *= inv; a.y *= inv; a.z *= inv; a.w *= inv;
  b.x *= inv; b.y *= inv; b.z *= inv; b.w *= inv;
  *reinterpret_cast<float4*>(p + lane * 4) = a;
  *reinterpret_cast<float4*>(p + 128 + lane * 4) = b;
}

extern "C" void kernel_launch(void* const* d_in, const int* in_sizes, int n_in,
                              void* d_out, int out_size) {
  const float* feat_left   = (const float*)d_in[0];
  const float* feat_right  = (const float*)d_in[1];
  const float* pos         = (const float*)d_in[2];
  const int*   pos_indexes = (const int*)d_in[3];
  const float* ln_w        = (const float*)d_in[4];
  const float* ln_b        = (const float*)d_in[5];
  const float* in_proj_w   = (const float*)d_in[6];
  const float* in_proj_b   = (const float*)d_in[7];
  const float* out_w       = (const float*)d_in[8];
  const float* out_b       = (const float*)d_in[9];
  float* out = (float*)d_out;

  ln_kernel<<<65536, 128>>>(feat_left, feat_right, ln_w, ln_b);

  gemm_k<0, 128, 128><<<dim3(4, 256, 1), 256>>>(
      nullptr, in_proj_w, in_proj_b, nullptr, nullptr, nullptr);
  gemm_k<1, 128, 128><<<dim3(8, 256, 1), 256>>>(
      nullptr, in_proj_w + 512 * 512, in_proj_b + 512, nullptr, nullptr, nullptr);
  gemm_k<2, 128, 128><<<dim3(8, 4, 1), 256>>>(
      pos, in_proj_w, in_proj_b, nullptr, nullptr, nullptr);

  gemm_k<3, 128, 128><<<dim3(2, 2, 1024), 256>>>(
      nullptr, nullptr, nullptr, nullptr, nullptr, nullptr);
  gemm_k<4, 128, 128><<<dim3(2, 1, 2048), 256>>>(
      nullptr, nullptr, nullptr, nullptr, pos_indexes, nullptr);
  gemm_k<5, 128, 128><<<dim3(1, 2, 2048), 256>>>(
      nullptr, nullptr, nullptr, nullptr, pos_indexes, nullptr);

  t3_add_kernel<<<dim3(256, 8), 256>>>();
  raw_kernel<<<32768, 256>>>(out + 16777216);
  softmax_kernel<<<32768, 256>>>();

  gemm_k<6, 128, 64><<<dim3(1, 2, 1024), 256>>>(
      nullptr, nullptr, nullptr, nullptr, nullptr, nullptr);
  gemm_k<7, 128, 128><<<dim3(4, 256, 1), 256>>>(
      nullptr, out_w, out_b, feat_left, nullptr, out);
}